// round 16
// baseline (speedup 1.0000x reference)
#include <cuda_runtime.h>

// HartleyCosineConv2d: y[n,c,h,w] = a0*x[h] + a1*(x[rf(h-1)]+x[rf(h+1)])
//                                 + a2*(x[rf(h-2)]+x[rf(h+2)]) + a3*(x[rf(h-3)]+x[rf(h+3)])
// reflect boundary: rf(i) = -i for i<0, rf(i) = 2H-2-i for i>=H.
//
// R16: granularity push. R15's 64-thr/1-plane blocks won 8.5us wall by
// halving the end-of-kernel drain quantum (kernel time ~flat, replay-
// averaged wall dropped). Extrapolate once more: split each plane in half
// along H -> grid 4096, 128 rows/block. Cost: 3-row halo per half (+1%
// total traffic); benefit: drain quantum halves again. Revert to R15 if
// wall >= 166.5us.

constexpr int H = 256;
constexpr int W = 256;
constexpr int C = 256;
constexpr int W4 = W / 4;            // 64 float4 per row
constexpr int H_HALF = H / 2;        // 128 rows per block

__device__ __forceinline__ float4 f4add(float4 a, float4 b) {
    return make_float4(a.x + b.x, a.y + b.y, a.z + b.z, a.w + b.w);
}

// r = a0*v3 + a1*(v2+v4) + a2*(v1+v5) + a3*(v0+n)
__device__ __forceinline__ float4 tap7(float a0, float a1, float a2, float a3,
                                       float4 v0, float4 v1, float4 v2,
                                       float4 v3, float4 v4, float4 v5,
                                       float4 n) {
    float4 s1 = f4add(v2, v4);
    float4 s2 = f4add(v1, v5);
    float4 s3 = f4add(v0, n);
    float4 r;
    r.x = fmaf(a0, v3.x, fmaf(a1, s1.x, fmaf(a2, s2.x, a3 * s3.x)));
    r.y = fmaf(a0, v3.y, fmaf(a1, s1.y, fmaf(a2, s2.y, a3 * s3.y)));
    r.z = fmaf(a0, v3.z, fmaf(a1, s1.z, fmaf(a2, s2.z, a3 * s3.z)));
    r.w = fmaf(a0, v3.w, fmaf(a1, s1.w, fmaf(a2, s2.w, a3 * s3.w)));
    return r;
}

__global__ __launch_bounds__(64)
void hartley_conv_kernel(const float4* __restrict__ x,
                         const float*  __restrict__ alpha,
                         float4*       __restrict__ y) {
    const int lane  = threadIdx.x;            // float4 column in row (0..63)
    const int plane = blockIdx.x >> 1;        // n*C + c
    const int half  = blockIdx.x & 1;         // 0: rows 0..127, 1: rows 128..255
    const int c     = plane & (C - 1);

    const size_t base = (size_t)plane * (H * W4) + lane;
    const float4* __restrict__ xp = x + base;
    float4*       __restrict__ yp = y + base;

    const float a0 = alpha[c * 4 + 0];
    const float a1 = alpha[c * 4 + 1];
    const float a2 = alpha[c * 4 + 2];
    const float a3 = alpha[c * 4 + 3];

    const int hb = half * H_HALF;             // first output row of this block

    // Window v0..v5 = rows rf(hb-3 .. hb+2).
    float4 v0, v1, v2, v3, v4, v5;
    if (half == 0) {
        // rf(-3..2) = 3,2,1,0,1,2 -> 4 distinct loads, reuse regs.
        float4 r3 = xp[3 * W4];
        float4 r2 = xp[2 * W4];
        float4 r1 = xp[1 * W4];
        float4 r0 = xp[0];
        v0 = r3; v1 = r2; v2 = r1; v3 = r0; v4 = r1; v5 = r2;
    } else {
        // Interior: rows 125..130 (3-row halo below hb=128).
        v0 = xp[(hb - 3) * W4];
        v1 = xp[(hb - 2) * W4];
        v2 = xp[(hb - 1) * W4];
        v3 = xp[(hb + 0) * W4];
        v4 = xp[(hb + 1) * W4];
        v5 = xp[(hb + 2) * W4];
    }

    for (int h0 = hb; h0 < hb + H_HALF; h0 += 8) {
        // rf(i) for i in [3, H+3): only upper reflection -> min(i, 2H-2-i)
        float4 nb[8];
        #pragma unroll
        for (int j = 0; j < 8; j++) {
            const int i = min(h0 + 3 + j, 2 * H - 2 - (h0 + 3 + j));
            nb[j] = xp[i * W4];          // 8 independent LDG.128 in flight
        }

        float4 ob[8];
        #pragma unroll
        for (int j = 0; j < 8; j++) {
            ob[j] = tap7(a0, a1, a2, a3, v0, v1, v2, v3, v4, v5, nb[j]);
            v0 = v1; v1 = v2; v2 = v3; v3 = v4; v4 = v5; v5 = nb[j];
        }

        #pragma unroll
        for (int j = 0; j < 8; j++)
            yp[(h0 + j) * W4] = ob[j];
    }
}

extern "C" void kernel_launch(void* const* d_in, const int* in_sizes, int n_in,
                              void* d_out, int out_size) {
    const float* x     = (const float*)d_in[0];
    const float* alpha = (const float*)d_in[1];
    float*       yout  = (float*)d_out;

    const int planes = in_sizes[0] / (H * W);   // N*C = 2048
    hartley_conv_kernel<<<planes * 2, 64>>>((const float4*)x, alpha, (float4*)yout);
}

// round 17
// speedup vs baseline: 1.0231x; 1.0231x over previous
#include <cuda_runtime.h>

// HartleyCosineConv2d: y[n,c,h,w] = a0*x[h] + a1*(x[rf(h-1)]+x[rf(h+1)])
//                                 + a2*(x[rf(h-2)]+x[rf(h+2)]) + a3*(x[rf(h-3)]+x[rf(h+3)])
// reflect boundary: rf(i) = -i for i<0, rf(i) = 2H-2-i for i>=H.
//
// FINAL champion (== R15). Granularity curve fully mapped:
//   grid 1024 (128thr/2 planes) -> 174.6us wall
//   grid 2048 ( 64thr/1 plane ) -> 166.0us wall   <== optimum
//   grid 4096 ( 64thr/half-plane, +halo) -> 170.0us wall
// Config:
//  - register sliding window along H: exactly 1 load + 1 store per element
//    (compulsory-minimal traffic, zero halo: 537MB r + 537MB w per call)
//  - float4 vectorization along W (LDG.128/STG.128, fully coalesced)
//  - unroll h by 8: 8 independent loads in flight per warp
//  - 64-thread blocks, 1 plane each, grid 2048: 54 regs, ~28 warps/SM,
//    single wave; fine CTA granularity minimizes end-of-kernel drain
//  - DEFAULT cache ops (evict hints / write-through / persist splits all
//    measured negative in R3/R5/R9)
// Measured: 160.1us kernel, 6410 GB/s = 80.9% DRAM — the mixed 1:1 r/w
// HBM3e ceiling on sm_103a. Issue=20%, L2=38%, pipes idle: memory-bound
// at the achievable roofline; bytes cannot shrink (fp32 contract, no reuse).

constexpr int H = 256;
constexpr int W = 256;
constexpr int C = 256;
constexpr int W4 = W / 4;            // 64 float4 per row

__device__ __forceinline__ float4 f4add(float4 a, float4 b) {
    return make_float4(a.x + b.x, a.y + b.y, a.z + b.z, a.w + b.w);
}

// r = a0*v3 + a1*(v2+v4) + a2*(v1+v5) + a3*(v0+n)
__device__ __forceinline__ float4 tap7(float a0, float a1, float a2, float a3,
                                       float4 v0, float4 v1, float4 v2,
                                       float4 v3, float4 v4, float4 v5,
                                       float4 n) {
    float4 s1 = f4add(v2, v4);
    float4 s2 = f4add(v1, v5);
    float4 s3 = f4add(v0, n);
    float4 r;
    r.x = fmaf(a0, v3.x, fmaf(a1, s1.x, fmaf(a2, s2.x, a3 * s3.x)));
    r.y = fmaf(a0, v3.y, fmaf(a1, s1.y, fmaf(a2, s2.y, a3 * s3.y)));
    r.z = fmaf(a0, v3.z, fmaf(a1, s1.z, fmaf(a2, s2.z, a3 * s3.z)));
    r.w = fmaf(a0, v3.w, fmaf(a1, s1.w, fmaf(a2, s2.w, a3 * s3.w)));
    return r;
}

__global__ __launch_bounds__(64)
void hartley_conv_kernel(const float4* __restrict__ x,
                         const float*  __restrict__ alpha,
                         float4*       __restrict__ y) {
    const int lane  = threadIdx.x;            // float4 column in row (0..63)
    const int plane = blockIdx.x;             // n*C + c
    const int c     = plane & (C - 1);

    const size_t base = (size_t)plane * (H * W4) + lane;
    const float4* __restrict__ xp = x + base;
    float4*       __restrict__ yp = y + base;

    const float a0 = alpha[c * 4 + 0];
    const float a1 = alpha[c * 4 + 1];
    const float a2 = alpha[c * 4 + 2];
    const float a3 = alpha[c * 4 + 3];

    // Window v0..v5 = rows rf(h-3 .. h+2); new tap n = row rf(h+3).
    // Prefill for h=0: rf(-3..2) = 3,2,1,0,1,2 -> 4 distinct loads, reuse regs.
    float4 r3 = xp[3 * W4];
    float4 r2 = xp[2 * W4];
    float4 r1 = xp[1 * W4];
    float4 r0 = xp[0];
    float4 v0 = r3, v1 = r2, v2 = r1, v3 = r0, v4 = r1, v5 = r2;

    for (int h0 = 0; h0 < H; h0 += 8) {
        // rf(i) for i in [3, H+3): only upper reflection -> min(i, 2H-2-i)
        float4 nb[8];
        #pragma unroll
        for (int j = 0; j < 8; j++) {
            const int i = min(h0 + 3 + j, 2 * H - 2 - (h0 + 3 + j));
            nb[j] = xp[i * W4];          // 8 independent LDG.128 in flight
        }

        float4 ob[8];
        #pragma unroll
        for (int j = 0; j < 8; j++) {
            ob[j] = tap7(a0, a1, a2, a3, v0, v1, v2, v3, v4, v5, nb[j]);
            v0 = v1; v1 = v2; v2 = v3; v3 = v4; v4 = v5; v5 = nb[j];
        }

        #pragma unroll
        for (int j = 0; j < 8; j++)
            yp[(h0 + j) * W4] = ob[j];
    }
}

extern "C" void kernel_launch(void* const* d_in, const int* in_sizes, int n_in,
                              void* d_out, int out_size) {
    const float* x     = (const float*)d_in[0];
    const float* alpha = (const float*)d_in[1];
    float*       yout  = (float*)d_out;

    const int planes = in_sizes[0] / (H * W);   // N*C = 2048
    hartley_conv_kernel<<<planes, 64>>>((const float4*)x, alpha, (float4*)yout);
}